// round 17
// baseline (speedup 1.0000x reference)
#include <cuda_runtime.h>
#include <cstdint>
#include <cuda_fp16.h>
#include <mma.h>
using namespace nvcuda;

// Problem constants
#define B_  4
#define T_  4096
#define D_  1024
#define H_  16
#define R_  256
#define DH_ 64
#define M_  16384   // B_*T_

// Scratch (allocation-free rule: __device__ globals)
__device__ __half g_Xh [16777216];  // x as fp16
__device__ __half g_Wfh[1310720];   // fused [Wq|Wd]  (1024 x 1280)
__device__ float  g_bqd[1280];      // fused bias [bq|bd]
__device__ __half g_Wuh[524288];
__device__ __half g_Woh[1048576];
__device__ __half g_Qh [16777216];  // (M,1024) q after elu+1
__device__ __half g_Ch [4194304];   // (M,256)  x@Wd+bd
__device__ __half g_Oh [16777216];  // (M,1024) attention out * z
__device__ float  g_ctx[262144];    // (B*H,64,64)
__device__ float  g_ksum[4096];     // (B*H,64)

__device__ __forceinline__ void f4_to_h4(const float4 v, __half* dst) {
    __half2 h0 = __floats2half2_rn(v.x, v.y);
    __half2 h1 = __floats2half2_rn(v.z, v.w);
    uint2 u;
    u.x = *reinterpret_cast<unsigned*>(&h0);
    u.y = *reinterpret_cast<unsigned*>(&h1);
    *reinterpret_cast<uint2*>(dst) = u;
}

// ---------------------------------------------------------------------------
// Fused prep: zero ctx/ksum, x->fp16, build [Wq|Wd] fp16 + fused bias,
// convert Wu/Wo. Segments in float4 units.
// ---------------------------------------------------------------------------
#define P_X    4194304
#define P_WF   (P_X + 327680)       // 4521984
#define P_WU   (P_WF + 131072)      // 4653056
#define P_WO   (P_WU + 262144)      // 4915200
#define P_BIAS (P_WO + 320)         // 4915520
#define P_CTX  (P_BIAS + 65536)     // 4981056
#define P_KS   (P_CTX + 1024)       // 4982080
#define PREP_BLOCKS ((P_KS + 255) / 256)

__global__ void prep_kernel(const float* __restrict__ x,
                            const float* __restrict__ Wq, const float* __restrict__ Wd,
                            const float* __restrict__ Wu, const float* __restrict__ Wo,
                            const float* __restrict__ bq, const float* __restrict__ bd) {
    int i = blockIdx.x * blockDim.x + threadIdx.x;
    if (i < P_X) {
        float4 v = reinterpret_cast<const float4*>(x)[i];
        f4_to_h4(v, &g_Xh[(size_t)i * 4]);
    } else if (i < P_WF) {
        int e = (i - P_X) * 4, r = e / 1280, c = e % 1280;
        float4 v = (c < 1024)
            ? *reinterpret_cast<const float4*>(&Wq[(size_t)r * 1024 + c])
            : *reinterpret_cast<const float4*>(&Wd[(size_t)r * 256 + c - 1024]);
        f4_to_h4(v, &g_Wfh[e]);
    } else if (i < P_WU) {
        int j = i - P_WF;
        float4 v = reinterpret_cast<const float4*>(Wu)[j];
        f4_to_h4(v, &g_Wuh[(size_t)j * 4]);
    } else if (i < P_WO) {
        int j = i - P_WU;
        float4 v = reinterpret_cast<const float4*>(Wo)[j];
        f4_to_h4(v, &g_Woh[(size_t)j * 4]);
    } else if (i < P_BIAS) {
        int e = (i - P_WO) * 4;
        float4 v = (e < 1024)
            ? *reinterpret_cast<const float4*>(&bq[e])
            : *reinterpret_cast<const float4*>(&bd[e - 1024]);
        *reinterpret_cast<float4*>(&g_bqd[e]) = v;
    } else if (i < P_CTX) {
        int j = i - P_BIAS;
        reinterpret_cast<float4*>(g_ctx)[j] = make_float4(0.f, 0.f, 0.f, 0.f);
    } else if (i < P_KS) {
        int j = i - P_CTX;
        reinterpret_cast<float4*>(g_ksum)[j] = make_float4(0.f, 0.f, 0.f, 0.f);
    }
}

// ---------------------------------------------------------------------------
// cp.async helpers
// ---------------------------------------------------------------------------
__device__ __forceinline__ void cp16(void* smem_dst, const void* gmem_src) {
    unsigned s = (unsigned)__cvta_generic_to_shared(smem_dst);
    asm volatile("cp.async.cg.shared.global [%0], [%1], 16;\n" :: "r"(s), "l"(gmem_src));
}
__device__ __forceinline__ void cp_commit() {
    asm volatile("cp.async.commit_group;\n" ::: "memory");
}
template<int N>
__device__ __forceinline__ void cp_wait() {
    asm volatile("cp.async.wait_group %0;\n" :: "n"(N) : "memory");
}

// ---------------------------------------------------------------------------
// fp16 WMMA GEMM. CTA tile 128x128x64, warp tile 32x64 (4x2 warps),
// 3-stage cp.async pipeline, ONE syncthreads per k-iter, 2 CTAs/SM.
// MODE 0: fused QD (cols<1024: elu+1 -> g_Qh; else -> g_Ch)
// MODE 1: KV+ctx fusion. CTA tile = 128 tokens x one head's [k|v].
//         Epilogue: bias+elu(k), fp16 tile in smem, then k^T v (64x64x128)
//         + ksum reduced IN-KERNEL via atomicAdd into g_ctx/g_ksum.
// MODE 2: plain float out (final)
// ---------------------------------------------------------------------------
#define BM 128
#define BN 128
#define BK 64
#define LDAh 72
#define LDBh 136
#define STAGE_Ah (BM * LDAh)   // 9216 halves
#define STAGE_Bh (BK * LDBh)   // 8704 halves
#define NSTAGE 3
#define GEMM_SMEM (NSTAGE * (STAGE_Ah + STAGE_Bh) * 2)   // 107520 B
#define KV_LD 136              // halves; 128x136 fp16 tile = 34816 B

template<int MODE>
__global__ __launch_bounds__(256, 2)
void gemm_f16(const __half* __restrict__ A, const __half* __restrict__ Bm,
              const float* __restrict__ bias, float* __restrict__ CoutF,
              int Ndim, int Kdim)
{
    extern __shared__ __half smh[];
    __half* Asm = smh;
    __half* Bsm = smh + NSTAGE * STAGE_Ah;

    const int tid  = threadIdx.x;
    const int warp = tid >> 5;
    const int lane = tid & 31;
    const int wm = warp >> 1;               // 0..3
    const int wn = warp & 1;                // 0..1
    const int row0 = blockIdx.y * BM;
    const int col0 = blockIdx.x * BN;
    const int Ktiles = Kdim / BK;

    // Hoisted per-thread staging offsets (constant across the k-loop).
    const unsigned a_soff = (unsigned)(tid >> 3) * LDAh + (tid & 7) * 8;
    const size_t   a_goff = (size_t)(tid >> 3) * Kdim + (tid & 7) * 8;
    const unsigned b_soff = (unsigned)(tid >> 4) * LDBh + (tid & 15) * 8;
    const size_t   b_goff = (size_t)(tid >> 4) * Ndim + (tid & 15) * 8;
    const __half* Abase = A + (size_t)row0 * Kdim + a_goff;
    const __half* Bbase = Bm + col0 + b_goff;

    auto issue = [&](int stage, int kt) {
        __half* as = Asm + stage * STAGE_Ah + a_soff;
        __half* bs = Bsm + stage * STAGE_Bh + b_soff;
        const __half* Ag = Abase + (size_t)kt * BK;
        const __half* Bg = Bbase + (size_t)kt * BK * Ndim;
        #pragma unroll
        for (int p = 0; p < 4; p++)          // A: 128 rows, 32/step
            cp16(as + p * 32 * LDAh, Ag + (size_t)p * 32 * Kdim);
        #pragma unroll
        for (int p = 0; p < 4; p++)          // B: 64 rows, 16/step
            cp16(bs + p * 16 * LDBh, Bg + (size_t)p * 16 * Ndim);
        cp_commit();
    };

    wmma::fragment<wmma::accumulator,16,16,16,float> acc[2][4];
    #pragma unroll
    for (int i = 0; i < 2; i++)
        #pragma unroll
        for (int j = 0; j < 4; j++) wmma::fill_fragment(acc[i][j], 0.f);

    issue(0, 0);
    if (Ktiles > 1) issue(1, 1);

    for (int kt = 0; kt < Ktiles; kt++) {
        if (kt + 1 < Ktiles) cp_wait<1>(); else cp_wait<0>();
        __syncthreads();

        const __half* as = Asm + (kt % NSTAGE) * STAGE_Ah;
        const __half* bs = Bsm + (kt % NSTAGE) * STAGE_Bh;

        #pragma unroll
        for (int kk = 0; kk < 4; kk++) {     // 4 x k=16
            wmma::fragment<wmma::matrix_a,16,16,16,__half,wmma::row_major> af[2];
            wmma::fragment<wmma::matrix_b,16,16,16,__half,wmma::row_major> bf[4];
            #pragma unroll
            for (int i = 0; i < 2; i++)
                wmma::load_matrix_sync(af[i], &as[(wm*32 + i*16)*LDAh + kk*16], LDAh);
            #pragma unroll
            for (int j = 0; j < 4; j++)
                wmma::load_matrix_sync(bf[j], &bs[(kk*16)*LDBh + wn*64 + j*16], LDBh);
            #pragma unroll
            for (int j = 0; j < 4; j++)
                #pragma unroll
                for (int i = 0; i < 2; i++)
                    wmma::mma_sync(acc[i][j], af[i], bf[j], acc[i][j]);
        }

        if (kt + 2 < Ktiles) issue((kt + 2) % NSTAGE, kt + 2);
    }

    __syncthreads();   // all warps done reading pipeline smem

    if (MODE != 1) {
        // Epilogue: per-warp float staging (32x68), then float4 stores.
        float* ep = reinterpret_cast<float*>(smh) + warp * (32 * 68);
        #pragma unroll
        for (int ii = 0; ii < 2; ii++)
            #pragma unroll
            for (int j = 0; j < 4; j++)
                wmma::store_matrix_sync(ep + (ii*16)*68 + j*16, acc[ii][j], 68,
                                        wmma::mem_row_major);
        __syncwarp();

        const int gr0 = row0 + wm * 32;
        const int gc0 = col0 + wn * 64;
        #pragma unroll
        for (int idx = lane; idx < 512; idx += 32) {   // 32 rows x 16 float4
            int rr = idx >> 4, c4 = (idx & 15) * 4;
            int gc = gc0 + c4;
            float4 v = *reinterpret_cast<const float4*>(&ep[rr*68 + c4]);
            float4 bb = *reinterpret_cast<const float4*>(&bias[gc]);
            v.x += bb.x; v.y += bb.y; v.z += bb.z; v.w += bb.w;
            int gr = gr0 + rr;
            if (MODE == 0) {
                if (gc < 1024) {
                    v.x = (v.x > 0.f) ? v.x + 1.f : __expf(v.x);
                    v.y = (v.y > 0.f) ? v.y + 1.f : __expf(v.y);
                    v.z = (v.z > 0.f) ? v.z + 1.f : __expf(v.z);
                    v.w = (v.w > 0.f) ? v.w + 1.f : __expf(v.w);
                    f4_to_h4(v, &g_Qh[(size_t)gr * 1024 + gc]);
                } else {
                    f4_to_h4(v, &g_Ch[(size_t)gr * 256 + (gc - 1024)]);
                }
            } else {
                *reinterpret_cast<float4*>(&CoutF[(size_t)gr * Ndim + gc]) = v;
            }
        }
    } else {
        // ---- MODE 1: KV tile -> smem fp16 + fused ctx/ksum reduction ----
        __half* KVs = smh;                                      // 128 x KV_LD
        float* ep = reinterpret_cast<float*>(
                        reinterpret_cast<char*>(smh) + 128 * KV_LD * 2)
                    + warp * (32 * 68);                         // 34816 + 69632 B

        #pragma unroll
        for (int ii = 0; ii < 2; ii++)
            #pragma unroll
            for (int j = 0; j < 4; j++)
                wmma::store_matrix_sync(ep + (ii*16)*68 + j*16, acc[ii][j], 68,
                                        wmma::mem_row_major);
        __syncwarp();

        const int gc0 = col0 + wn * 64;
        #pragma unroll
        for (int idx = lane; idx < 512; idx += 32) {   // 32 rows x 16 float4
            int rr = idx >> 4, c4 = (idx & 15) * 4;
            int lc = wn * 64 + c4;                      // local col 0..127
            float4 v = *reinterpret_cast<const float4*>(&ep[rr*68 + c4]);
            float4 bb = *reinterpret_cast<const float4*>(&bias[gc0 + c4]);
            v.x += bb.x; v.y += bb.y; v.z += bb.z; v.w += bb.w;
            if (lc < 64) {                              // k half: elu+1
                v.x = (v.x > 0.f) ? v.x + 1.f : __expf(v.x);
                v.y = (v.y > 0.f) ? v.y + 1.f : __expf(v.y);
                v.z = (v.z > 0.f) ? v.z + 1.f : __expf(v.z);
                v.w = (v.w > 0.f) ? v.w + 1.f : __expf(v.w);
            }
            f4_to_h4(v, &KVs[(wm*32 + rr) * KV_LD + lc]);
        }
        __syncthreads();   // full [k|v] fp16 tile visible

        // ctx partial: K^T V, 64x64 over 128 tokens.
        const int ti  = warp >> 1;
        const int tj0 = (warp & 1) * 2;
        wmma::fragment<wmma::accumulator,16,16,16,float> acc2[2];
        #pragma unroll
        for (int j = 0; j < 2; j++) wmma::fill_fragment(acc2[j], 0.f);
        #pragma unroll
        for (int ks = 0; ks < 8; ks++) {
            int t0 = ks * 16;
            wmma::fragment<wmma::matrix_a,16,16,16,__half,wmma::col_major> af2;
            wmma::load_matrix_sync(af2, &KVs[t0 * KV_LD + ti * 16], KV_LD);
            #pragma unroll
            for (int j = 0; j < 2; j++) {
                wmma::fragment<wmma::matrix_b,16,16,16,__half,wmma::row_major> bf2;
                wmma::load_matrix_sync(bf2, &KVs[t0 * KV_LD + 64 + (tj0 + j) * 16], KV_LD);
                wmma::mma_sync(acc2[j], af2, bf2, acc2[j]);
            }
        }

        // ksum partial: 4 groups of 32 tokens per d.
        const int kd = tid & 63, kq = tid >> 6;
        float kssum = 0.f;
        #pragma unroll 8
        for (int t = kq * 32; t < kq * 32 + 32; t++)
            kssum += __half2float(KVs[t * KV_LD + kd]);

        // Stage ctx partials and atomically reduce.
        float* buf = ep;
        wmma::store_matrix_sync(buf,      acc2[0], 68, wmma::mem_row_major);
        wmma::store_matrix_sync(buf + 16, acc2[1], 68, wmma::mem_row_major);
        __syncwarp();

        const int bh = (row0 >> 12) * 16 + (col0 >> 7);
        float* ctxp = g_ctx + bh * 4096;
        #pragma unroll
        for (int t = lane; t < 16 * 32; t += 32) {   // 16 rows x 32 cols
            int rr = t >> 5, cc = t & 31;
            atomicAdd(&ctxp[(ti * 16 + rr) * 64 + tj0 * 16 + cc], buf[rr * 68 + cc]);
        }
        atomicAdd(&g_ksum[bh * 64 + kd], kssum);
    }
}

// ---------------------------------------------------------------------------
// out = (q @ ctx) * 1/(q . ksum + 1e-6).  fp16 WMMA; normalizer in fp32.
// 256 threads; block covers 512 tokens (4 iters of 128; warps 0-3 tile A,
// warps 4-7 tile B). ctx/ksum loaded once. Dynamic smem layout (bytes):
//   Qsh  [128 x 72 halves]  18432
//   Csh  [ 64 x 72 halves]   9216
//   ksf  [64 f32]             256
//   zinv [128 f32]            512
//   Fst  [8 warps x 16x68 f32] 34816     total 63232
// Epilogue: per-warp fp32 staging -> zinv scale -> fp16 -> uint4 STG.
// grid (64 bh, 8 groups).
// ---------------------------------------------------------------------------
#define AO_QSH  0
#define AO_CSH  18432
#define AO_KSF  (AO_CSH + 9216)
#define AO_ZNV  (AO_KSF + 256)
#define AO_FST  (AO_ZNV + 512)
#define AO_SMEM (AO_FST + 34816)   // 63232 B

__global__ __launch_bounds__(256)
void attn_out_kernel()
{
    extern __shared__ char aosm[];
    __half* Qsh  = reinterpret_cast<__half*>(aosm + AO_QSH);   // ld 72
    __half* Csh  = reinterpret_cast<__half*>(aosm + AO_CSH);   // ld 72
    float*  ksf  = reinterpret_cast<float*>(aosm + AO_KSF);
    float*  zinv = reinterpret_cast<float*>(aosm + AO_ZNV);
    float*  Fst  = reinterpret_cast<float*>(aosm + AO_FST);    // 8 x 16x68

    const int bh = blockIdx.x;
    const int grp = blockIdx.y;          // 0..7, each 512 tokens
    const int b = bh >> 4, h = bh & 15;
    const int tid = threadIdx.x;
    const int warp = tid >> 5, lane = tid & 31;
    const int half_id = warp >> 2;       // 0: tokens 0-63, 1: tokens 64-127
    const int wsub = warp & 3;           // 16-token row slice within half

    // Load ctx + ksum once per block.
    const float* cp = g_ctx + bh * 4096;
    for (int i = tid; i < 4096; i += 256) {
        int d = i >> 6, e = i & 63;
        Csh[d * 72 + e] = __float2half_rn(cp[i]);
    }
    if (tid < 64) ksf[tid] = g_ksum[bh * 64 + tid];

    for (int sub = 0; sub < 4; sub++) {
        int t0 = grp * 512 + sub * 128;  // first token of this 128-token pair
        __syncthreads();                 // prior iter reads done; Csh/ksf ready

        // Stage 128 tokens of Q (each thread: 4 x 16B chunks)
        const __half* Qb = g_Qh + (size_t)(b * T_ + t0) * 1024 + h * 64;
        #pragma unroll
        for (int p = 0; p < 4; p++) {    // 1024 chunks of 8 halves
            int idx = tid + p * 256;
            int r = idx >> 3, c = (idx & 7) * 8;
            *reinterpret_cast<uint4*>(&Qsh[r * 72 + c]) =
                *reinterpret_cast<const uint4*>(Qb + (size_t)r * 1024 + c);
        }
        __syncthreads();

        // fp32 normalizer for 128 tokens
        if (tid < 128) {
            float s = 0.f;
            #pragma unroll 16
            for (int d = 0; d < 64; d++)
                s += __half2float(Qsh[tid * 72 + d]) * ksf[d];
            zinv[tid] = 1.f / (s + 1e-6f);
        }

        // Each warp: 16 tokens x 64 cols. Row base = half_id*64 + wsub*16.
        const int rbase = half_id * 64 + wsub * 16;
        wmma::fragment<wmma::accumulator,16,16,16,float> acc[4];
        #pragma unroll
        for (int j = 0; j < 4; j++) wmma::fill_fragment(acc[j], 0.f);

        #pragma unroll
        for (int k = 0; k < 4; k++) {
            wmma::fragment<wmma::matrix_a,16,16,16,__half,wmma::row_major> af;
            wmma::load_matrix_sync(af, &Qsh[rbase * 72 + k * 16], 72);
            #pragma unroll
            for (int j = 0; j < 4; j++) {
                wmma::fragment<wmma::matrix_b,16,16,16,__half,wmma::row_major> bf;
                wmma::load_matrix_sync(bf, &Csh[(k * 16) * 72 + j * 16], 72);
                wmma::mma_sync(acc[j], af, bf, acc[j]);
            }
        }
        __syncthreads();                 // zinv ready; Qsh reads done

        // Per-warp fp32 staging, then zinv scale + fp16 + uint4 global store.
        float* fbuf = Fst + warp * (16 * 68);
        #pragma unroll
        for (int j = 0; j < 4; j++)
            wmma::store_matrix_sync(fbuf + j * 16, acc[j], 68, wmma::mem_row_major);
        __syncwarp();

        __half* Ob = g_Oh + (size_t)(b * T_ + t0 + rbase) * 1024 + h * 64;
        #pragma unroll
        for (int t = lane; t < 128; t += 32) {   // 16 rows x 8 chunks of 8
            int rr = t >> 3, c8 = (t & 7) * 8;
            float z = zinv[rbase + rr];
            const float* fr = fbuf + rr * 68 + c8;
            __half2 h0 = __floats2half2_rn(fr[0] * z, fr[1] * z);
            __half2 h1 = __floats2half2_rn(fr[2] * z, fr[3] * z);
            __half2 h2 = __floats2half2_rn(fr[4] * z, fr[5] * z);
            __half2 h3 = __floats2half2_rn(fr[6] * z, fr[7] * z);
            uint4 u;
            u.x = *reinterpret_cast<unsigned*>(&h0);
            u.y = *reinterpret_cast<unsigned*>(&h1);
            u.z = *reinterpret_cast<unsigned*>(&h2);
            u.w = *reinterpret_cast<unsigned*>(&h3);
            *reinterpret_cast<uint4*>(Ob + (size_t)rr * 1024 + c8) = u;
        }
    }
}

// ---------------------------------------------------------------------------
extern "C" void kernel_launch(void* const* d_in, const int* in_sizes, int n_in,
                              void* d_out, int out_size)
{
    const float* x  = (const float*)d_in[0];
    const float* Wq = (const float*)d_in[1];
    const float* bq = (const float*)d_in[2];
    const float* Wd = (const float*)d_in[3];
    const float* bd = (const float*)d_in[4];
    const float* Wu = (const float*)d_in[5];
    const float* bu = (const float*)d_in[6];
    const float* Wo = (const float*)d_in[7];
    const float* bo = (const float*)d_in[8];
    float* out = (float*)d_out;

    void *pXh, *pWfh, *pbqd, *pWuh, *pWoh, *pCh, *pOh;
    cudaGetSymbolAddress(&pXh,  g_Xh);
    cudaGetSymbolAddress(&pWfh, g_Wfh);
    cudaGetSymbolAddress(&pbqd, g_bqd);
    cudaGetSymbolAddress(&pWuh, g_Wuh);
    cudaGetSymbolAddress(&pWoh, g_Woh);
    cudaGetSymbolAddress(&pCh,  g_Ch);
    cudaGetSymbolAddress(&pOh,  g_Oh);

    cudaFuncSetAttribute(gemm_f16<0>, cudaFuncAttributeMaxDynamicSharedMemorySize, GEMM_SMEM);
    cudaFuncSetAttribute(gemm_f16<1>, cudaFuncAttributeMaxDynamicSharedMemorySize, GEMM_SMEM);
    cudaFuncSetAttribute(gemm_f16<2>, cudaFuncAttributeMaxDynamicSharedMemorySize, GEMM_SMEM);
    cudaFuncSetAttribute(attn_out_kernel, cudaFuncAttributeMaxDynamicSharedMemorySize, AO_SMEM);

    prep_kernel<<<PREP_BLOCKS, 256>>>(x, Wq, Wd, Wu, Wo, bq, bd);

    // [Q|C] = x @ [Wq|Wd] + [bq|bd], elu+1 on Q half.  grid: (N tiles, M tiles)
    gemm_f16<0><<<dim3(1280/BN, M_/BM), 256, GEMM_SMEM>>>(
        (const __half*)pXh, (const __half*)pWfh, (const float*)pbqd, nullptr, 1280, 1024);
    // KV = C@Wu + bu with FUSED ctx/ksum reduction (no KV materialization)
    gemm_f16<1><<<dim3(2048/BN, M_/BM), 256, GEMM_SMEM>>>(
        (const __half*)pCh, (const __half*)pWuh, bu, nullptr, 2048, 256);

    attn_out_kernel<<<dim3(64, 8), 256, AO_SMEM>>>();

    // out = O@Wo + bo
    gemm_f16<2><<<dim3(1024/BN, M_/BM), 256, GEMM_SMEM>>>(
        (const __half*)pOh, (const __half*)pWoh, bo, out, 1024, 1024);
}